// round 14
// baseline (speedup 1.0000x reference)
#include <cuda_runtime.h>
#include <cuda_bf16.h>
#include <cstdint>

static constexpr int NB  = 2;
static constexpr int S   = 4096;
static constexpr int CIN = 2048;
static constexpr int RC  = 512;
static constexpr int OC  = 4096;
static constexpr int NZ  = 2 * NB;       // branches x batch
static constexpr int MG  = OC / 128;     // 32 partial-sum row groups (conv2 grid.y)

// ---------------- device scratch (bf16) --------------------------------------
__device__ __align__(16) __nv_bfloat16 g_xh [(size_t)NB * CIN * S];
__device__ __align__(16) __nv_bfloat16 g_wrh[2][(size_t)RC * CIN];
__device__ __align__(16) __nv_bfloat16 g_w1h[2][(size_t)RC * RC];
__device__ __align__(16) __nv_bfloat16 g_w2h[2][(size_t)OC * RC];
__device__ __align__(16) __nv_bfloat16 g_redh[(size_t)NZ * RC * S];
__device__ __align__(16) __nv_bfloat16 g_hh [(size_t)NZ * RC * S];
__device__ __align__(16) __nv_bfloat16 g_ah [(size_t)NZ * OC * S];   // exp map
__device__ float g_z [NZ * S];
__device__ float g_pz[(size_t)MG * NZ * S];   // partial column sums

// ---------------- helpers ----------------------------------------------------
#define SW(o) ((o) ^ (((o) >> 3) & 0x70))

__device__ __forceinline__ uint32_t s2u(const void* p) {
    uint32_t a;
    asm("{ .reg .u64 t; cvta.to.shared.u64 t, %1; cvt.u32.u64 %0, t; }"
        : "=r"(a) : "l"(p));
    return a;
}

__device__ __forceinline__ void cpa16(uint32_t s, const void* g) {
    asm volatile("cp.async.cg.shared.global [%0], [%1], 16;" :: "r"(s), "l"(g));
}

#define CP_COMMIT() asm volatile("cp.async.commit_group;" ::: "memory")
#define CP_WAIT0()  asm volatile("cp.async.wait_group 0;" ::: "memory")

#define LDSM4(r, a)                                                            \
    asm volatile("ldmatrix.sync.aligned.m8n8.x4.shared.b16 {%0,%1,%2,%3}, [%4];" \
                 : "=r"((r)[0]), "=r"((r)[1]), "=r"((r)[2]), "=r"((r)[3])      \
                 : "r"(a))

#define LDSM4T(r, a)                                                           \
    asm volatile("ldmatrix.sync.aligned.m8n8.x4.trans.shared.b16 {%0,%1,%2,%3}, [%4];" \
                 : "=r"((r)[0]), "=r"((r)[1]), "=r"((r)[2]), "=r"((r)[3])      \
                 : "r"(a))

__device__ __forceinline__ void mma16816(float* d, const uint32_t* a,
                                         const uint32_t* b) {
    asm volatile(
        "mma.sync.aligned.m16n8k16.row.col.f32.bf16.bf16.f32 "
        "{%0,%1,%2,%3}, {%4,%5,%6,%7}, {%8,%9}, {%0,%1,%2,%3};"
        : "+f"(d[0]), "+f"(d[1]), "+f"(d[2]), "+f"(d[3])
        : "r"(a[0]), "r"(a[1]), "r"(a[2]), "r"(a[3]), "r"(b[0]), "r"(b[1]));
}

// SMEM stage: A 16K | B 8K = 24K; 2 stages = 48K
static constexpr int STG    = 24576;
static constexpr int OFF_B  = 16384;
static constexpr int SMEM_BYTES = 2 * STG;

enum { EPL_BNRELU = 0, EPL_EXP = 1, EPF_DIV = 2 };

struct GP {
    const __nv_bfloat16 *Ah[2], *Bh[2];
    __nv_bfloat16 *Ch[2];
    float *Cf[2];
    const float *bn[2], *z[2];
    float *psum;
    int M, K, N;
    size_t aBS, bBS, cBS;
};

// ======== bf16 tensor GEMM (both branches): C = A @ B =======================
// CTA tile 128x64, 8 warps (4x2), warp tile 32x32, K-chunk 64, 2 CTAs/SM.
// Fragments are double-buffered in registers: ldsm(ks+1) overlaps mma(ks).
template <int EP>
__global__ void __launch_bounds__(256, 2)
gemm_mma(GP p)
{
    extern __shared__ char smem[];
    const uint32_t sb = s2u(smem);
    const int t = threadIdx.x, wid = t >> 5, lane = t & 31;
    const int br = blockIdx.z >> 1, bz = blockIdx.z & 1;
    const int m0 = blockIdx.y * 128, n0 = blockIdx.x * 64;
    const int wm0 = (wid >> 1) * 32, wn0 = (wid & 1) * 32;
    const int K = p.K, N = p.N;

    const __nv_bfloat16* Abh = p.Ah[br] + bz * p.aBS + (size_t)m0 * K;
    const __nv_bfloat16* Bbh = p.Bh[br] + bz * p.bBS + n0;

    const int a_r = t >> 3, a_c = t & 7;

    auto load_chunk = [&](int k0, int stg) {
        const uint32_t st = sb + stg * STG;
#pragma unroll
        for (int it = 0; it < 4; it++) {
            int row = it * 32 + a_r;
            uint32_t d = (uint32_t)SW(row * 128 + a_c * 16);
            size_t so = (size_t)row * K + k0 + a_c * 8;
            cpa16(st + d, Abh + so);
        }
#pragma unroll
        for (int it = 0; it < 2; it++) {
            int idx = it * 256 + t;
            int row = idx >> 3, nc = idx & 7;
            uint32_t d = (uint32_t)SW(row * 128 + nc * 16);
            size_t so = (size_t)(k0 + row) * N + nc * 8;
            cpa16(st + OFF_B + d, Bbh + so);
        }
        CP_COMMIT();
    };

    float acc[2][4][4];
#pragma unroll
    for (int i = 0; i < 2; i++)
#pragma unroll
        for (int j = 0; j < 4; j++)
#pragma unroll
            for (int q = 0; q < 4; q++) acc[i][j][q] = 0.f;

    const int la_r = lane & 15, la_k = lane >> 4;
    const int bt_k = ((lane >> 3) & 1) * 8 + (lane & 7);
    const int bt_n = (lane >> 4) * 8;

    // fragment loader: one ks step (2 A LDSM4 + 2 B LDSM4T)
    auto ldfrag = [&](uint32_t st, int ks, uint32_t (&ar)[2][4], uint32_t (&br2)[2][4]) {
#pragma unroll
        for (int i = 0; i < 2; i++) {
            uint32_t d = (uint32_t)SW((wm0 + 16 * i + la_r) * 128 +
                                      ks * 32 + la_k * 16);
            LDSM4(ar[i], st + d);
        }
#pragma unroll
        for (int jj = 0; jj < 2; jj++) {
            uint32_t d = (uint32_t)SW((ks * 16 + bt_k) * 128 +
                                      (wn0 + 16 * jj + bt_n) * 2);
            LDSM4T(br2[jj], st + OFF_B + d);
        }
    };

    const int nc = K / 64;
    load_chunk(0, 0);

    uint32_t ah[2][2][4], bh[2][2][4];   // [buf][frag][regs]

    for (int ci = 0; ci < nc; ci++) {
        const int stg = ci & 1;
        CP_WAIT0();
        __syncthreads();
        if (ci + 1 < nc) load_chunk((ci + 1) * 64, stg ^ 1);

        const uint32_t st = sb + stg * STG;
        ldfrag(st, 0, ah[0], bh[0]);
#pragma unroll
        for (int ks = 0; ks < 4; ks++) {
            const int cur = ks & 1;
            if (ks < 3) ldfrag(st, ks + 1, ah[cur ^ 1], bh[cur ^ 1]);
#pragma unroll
            for (int i = 0; i < 2; i++)
#pragma unroll
                for (int j = 0; j < 4; j++)
                    mma16816(acc[i][j], ah[cur][i], &bh[cur][j >> 1][(j & 1) * 2]);
        }
        __syncthreads();   // keeps warps converged; removing this cost 50% (R6)
    }

    // ---------------- epilogue ----------------
    const int g  = lane >> 2;
    const int t2 = lane & 3;

    float cs[4][2];           // column-sum partials (EXP only)
#pragma unroll
    for (int j = 0; j < 4; j++) { cs[j][0] = 0.f; cs[j][1] = 0.f; }

#pragma unroll
    for (int i = 0; i < 2; i++) {
        const int r0 = m0 + wm0 + 16 * i + g;
        const int r1 = r0 + 8;
        float sc0 = 1.f, sh0 = 0.f, sc1 = 1.f, sh1 = 0.f;
        if (EP == EPL_BNRELU) {
            const float* bnp = p.bn[br];
            float ga = bnp[r0], be = bnp[p.M + r0], mu = bnp[2 * p.M + r0], va = bnp[3 * p.M + r0];
            sc0 = ga * rsqrtf(va + 1e-5f);
            sh0 = be - mu * sc0;
            ga = bnp[r1]; be = bnp[p.M + r1]; mu = bnp[2 * p.M + r1]; va = bnp[3 * p.M + r1];
            sc1 = ga * rsqrtf(va + 1e-5f);
            sh1 = be - mu * sc1;
        }
#pragma unroll
        for (int j = 0; j < 4; j++) {
            const int c = n0 + wn0 + 8 * j + t2 * 2;
            float v0 = acc[i][j][0], v1 = acc[i][j][1];
            float v2 = acc[i][j][2], v3 = acc[i][j][3];
            if (EP == EPL_BNRELU) {
                v0 = fmaxf(v0 * sc0 + sh0, 0.f);
                v1 = fmaxf(v1 * sc0 + sh0, 0.f);
                v2 = fmaxf(v2 * sc1 + sh1, 0.f);
                v3 = fmaxf(v3 * sc1 + sh1, 0.f);
            }
            if (EP == EPL_EXP) {
                v0 = __expf(v0); v1 = __expf(v1);
                v2 = __expf(v2); v3 = __expf(v3);
                cs[j][0] += v0 + v2;
                cs[j][1] += v1 + v3;
            }
            if (EP == EPF_DIV) {
                const float* zb = p.z[br] + (size_t)bz * N + c;
                float z0 = zb[0], z1 = zb[1];
                float* Cb = p.Cf[br] + bz * p.cBS;
                *(float2*)(Cb + (size_t)r0 * N + c) = make_float2(v0 / z0, v1 / z1);
                *(float2*)(Cb + (size_t)r1 * N + c) = make_float2(v2 / z0, v3 / z1);
            } else {
                uint32_t h0, h1;
                asm("cvt.rn.bf16x2.f32 %0, %1, %2;" : "=r"(h0) : "f"(v1), "f"(v0));
                asm("cvt.rn.bf16x2.f32 %0, %1, %2;" : "=r"(h1) : "f"(v3), "f"(v2));
                size_t cb0 = bz * p.cBS + (size_t)r0 * N + c;
                size_t cb1 = bz * p.cBS + (size_t)r1 * N + c;
                *(uint32_t*)(p.Ch[br] + cb0) = h0;
                *(uint32_t*)(p.Ch[br] + cb1) = h1;
            }
        }
    }

    if (EP == EPL_EXP) {
        // reduce over the 8 row-lanes (lane bits 2..4) of this warp
#pragma unroll
        for (int off = 4; off < 32; off <<= 1)
#pragma unroll
            for (int j = 0; j < 4; j++) {
                cs[j][0] += __shfl_xor_sync(0xffffffffu, cs[j][0], off);
                cs[j][1] += __shfl_xor_sync(0xffffffffu, cs[j][1], off);
            }
        __syncthreads();            // tile smem no longer needed; reuse it
        float* cs_buf = (float*)smem;   // [8 warps][32 cols]
        if (lane < 4) {
#pragma unroll
            for (int j = 0; j < 4; j++) {
                cs_buf[wid * 32 + 8 * j + 2 * lane]     = cs[j][0];
                cs_buf[wid * 32 + 8 * j + 2 * lane + 1] = cs[j][1];
            }
        }
        __syncthreads();
        if (t < 64) {
            int half = t >> 5, lc = t & 31;
            float s = 0.f;
#pragma unroll
            for (int rw = 0; rw < 4; rw++)
                s += cs_buf[(rw * 2 + half) * 32 + lc];
            p.psum[(size_t)blockIdx.y * (NZ * S) + (size_t)blockIdx.z * S + n0 + t] = s;
        }
    }
}

// ================= fp32 -> bf16 conversions =================================
__global__ void to_hi(const float4* __restrict__ src, uint2* __restrict__ hi, int n4)
{
    int i = blockIdx.x * blockDim.x + threadIdx.x;
    if (i >= n4) return;
    float4 f = src[i];
    uint2 h;
    asm("cvt.rn.bf16x2.f32 %0, %1, %2;" : "=r"(h.x) : "f"(f.y), "f"(f.x));
    asm("cvt.rn.bf16x2.f32 %0, %1, %2;" : "=r"(h.y) : "f"(f.w), "f"(f.z));
    hi[i] = h;
}

__global__ void to_hi3(const float4* s0, uint2* h0, int n0,
                       const float4* s1, uint2* h1, int n1,
                       const float4* s2, uint2* h2, int n2)
{
    int i = blockIdx.x * blockDim.x + threadIdx.x;
    const float4* s; uint2* hp; int idx;
    if (i < n0)           { s = s0; hp = h0; idx = i; }
    else if (i < n0 + n1) { s = s1; hp = h1; idx = i - n0; }
    else if (i < n0 + n1 + n2) { s = s2; hp = h2; idx = i - n0 - n1; }
    else return;
    float4 f = s[idx];
    uint2 h;
    asm("cvt.rn.bf16x2.f32 %0, %1, %2;" : "=r"(h.x) : "f"(f.y), "f"(f.x));
    asm("cvt.rn.bf16x2.f32 %0, %1, %2;" : "=r"(h.y) : "f"(f.w), "f"(f.z));
    hp[idx] = h;
}

// ============ reduce MG partial column sums -> Z (deterministic) ============
__global__ void reduce_sum(const float* __restrict__ part, float* __restrict__ outv)
{
    const int i = blockIdx.x * blockDim.x + threadIdx.x;
    if (i >= NZ * S) return;
    float v = 0.f;
#pragma unroll
    for (int c = 0; c < MG; c++)
        v += part[(size_t)c * (NZ * S) + i];
    outv[i] = v;
}

// ================= launch ====================================================
extern "C" void kernel_launch(void* const* d_in, const int* in_sizes, int n_in,
                              void* d_out, int out_size)
{
    (void)in_sizes; (void)n_in; (void)out_size;
    const float* x = (const float*)d_in[0];
    float* out = (float*)d_out;

    __nv_bfloat16 *xh, *redh, *hh, *ah;
    __nv_bfloat16 *wrh, *w1h, *w2h;
    float *z_, *pz_;
    cudaGetSymbolAddress((void**)&xh, g_xh);
    cudaGetSymbolAddress((void**)&wrh, g_wrh);
    cudaGetSymbolAddress((void**)&w1h, g_w1h);
    cudaGetSymbolAddress((void**)&w2h, g_w2h);
    cudaGetSymbolAddress((void**)&redh, g_redh);
    cudaGetSymbolAddress((void**)&hh, g_hh);
    cudaGetSymbolAddress((void**)&ah, g_ah);
    cudaGetSymbolAddress((void**)&z_, g_z);
    cudaGetSymbolAddress((void**)&pz_, g_pz);

    const size_t WR = (size_t)RC * CIN, W1 = (size_t)RC * RC, W2 = (size_t)OC * RC;

    cudaFuncSetAttribute((const void*)gemm_mma<EPL_BNRELU>,
                         cudaFuncAttributeMaxDynamicSharedMemorySize, SMEM_BYTES);
    cudaFuncSetAttribute((const void*)gemm_mma<EPL_EXP>,
                         cudaFuncAttributeMaxDynamicSharedMemorySize, SMEM_BYTES);
    cudaFuncSetAttribute((const void*)gemm_mma<EPF_DIV>,
                         cudaFuncAttributeMaxDynamicSharedMemorySize, SMEM_BYTES);

    // [0] x -> bf16
    {
        int n4 = NB * CIN * S / 4;
        to_hi<<<(n4 + 255) / 256, 256>>>((const float4*)x, (uint2*)xh, n4);
    }
    // [1],[2] weights -> bf16
    for (int br = 0; br < 2; br++) {
        const float* wred = (const float*)d_in[1 + br * 5 + 0];
        const float* w1   = (const float*)d_in[1 + br * 5 + 2];
        const float* w2   = (const float*)d_in[1 + br * 5 + 4];
        int n0 = (int)(WR / 4), n1 = (int)(W1 / 4), n2 = (int)(W2 / 4);
        int nb = (n0 + n1 + n2 + 255) / 256;
        to_hi3<<<nb, 256>>>(
            (const float4*)wred, (uint2*)(wrh + br * WR), n0,
            (const float4*)w1,   (uint2*)(w1h + br * W1), n1,
            (const float4*)w2,   (uint2*)(w2h + br * W2), n2);
    }

    const float* bn1c = (const float*)d_in[2];
    const float* bn2c = (const float*)d_in[4];
    const float* bn1d = (const float*)d_in[7];
    const float* bn2d = (const float*)d_in[9];

    GP p{};
    // [3] reduce: red = relu(bn1(wred @ x))
    p.Ah[0] = wrh; p.Ah[1] = wrh + WR;
    p.Bh[0] = p.Bh[1] = xh;
    p.Ch[0] = redh; p.Ch[1] = redh + (size_t)NB * RC * S;
    p.bn[0] = bn1c; p.bn[1] = bn1d;
    p.M = RC; p.K = CIN; p.N = S;
    p.aBS = 0; p.bBS = (size_t)CIN * S; p.cBS = (size_t)RC * S;
    gemm_mma<EPL_BNRELU><<<dim3(S / 64, RC / 128, NZ), 256, SMEM_BYTES>>>(p);

    // [4] conv1: h = relu(bn2(w1 @ red))
    p.Ah[0] = w1h; p.Ah[1] = w1h + W1;
    p.Bh[0] = redh; p.Bh[1] = redh + (size_t)NB * RC * S;
    p.Ch[0] = hh; p.Ch[1] = hh + (size_t)NB * RC * S;
    p.bn[0] = bn2c; p.bn[1] = bn2d;
    p.M = RC; p.K = RC; p.N = S;
    p.aBS = 0; p.bBS = (size_t)RC * S; p.cBS = (size_t)RC * S;
    gemm_mma<EPL_BNRELU><<<dim3(S / 64, RC / 128, NZ), 256, SMEM_BYTES>>>(p);

    // [5] conv2 + fused exp + partial column sums: expA = exp(w2 @ h)
    p.Ah[0] = w2h; p.Ah[1] = w2h + W2;
    p.Bh[0] = hh; p.Bh[1] = hh + (size_t)NB * RC * S;
    p.Ch[0] = ah; p.Ch[1] = ah + (size_t)NB * OC * S;
    p.psum = pz_;
    p.M = OC; p.K = RC; p.N = S;
    p.aBS = 0; p.bBS = (size_t)RC * S; p.cBS = (size_t)OC * S;
    gemm_mma<EPL_EXP><<<dim3(S / 64, OC / 128, NZ), 256, SMEM_BYTES>>>(p);

    // [6] Z = sum of MG partials (deterministic)
    reduce_sum<<<(NZ * S + 255) / 256, 256>>>(pz_, z_);

    // [7] bmm: fm = red @ expA / Z -> out
    p.Ah[0] = redh; p.Ah[1] = redh + (size_t)NB * RC * S;
    p.Bh[0] = ah; p.Bh[1] = ah + (size_t)NB * OC * S;
    p.Cf[0] = out; p.Cf[1] = out + (size_t)RC * S;
    p.z[0] = z_; p.z[1] = z_ + (size_t)NB * S;
    p.M = RC; p.K = S; p.N = S;
    p.aBS = (size_t)RC * S; p.bBS = (size_t)S * S; p.cBS = (size_t)2 * RC * S;
    gemm_mma<EPF_DIV><<<dim3(S / 64, RC / 128, NZ), 256, SMEM_BYTES>>>(p);
}

// round 15
// speedup vs baseline: 1.0616x; 1.0616x over previous
#include <cuda_runtime.h>
#include <cuda_bf16.h>
#include <cstdint>

static constexpr int NB  = 2;
static constexpr int S   = 4096;
static constexpr int CIN = 2048;
static constexpr int RC  = 512;
static constexpr int OC  = 4096;
static constexpr int NZ  = 2 * NB;       // branches x batch
static constexpr int MG  = OC / 128;     // 32 partial-sum row groups (conv2 grid.y)

// ---------------- device scratch (bf16) --------------------------------------
__device__ __align__(16) __nv_bfloat16 g_xh [(size_t)NB * CIN * S];
__device__ __align__(16) __nv_bfloat16 g_wrh[2][(size_t)RC * CIN];
__device__ __align__(16) __nv_bfloat16 g_w1h[2][(size_t)RC * RC];
__device__ __align__(16) __nv_bfloat16 g_w2h[2][(size_t)OC * RC];
__device__ __align__(16) __nv_bfloat16 g_redh[(size_t)NZ * RC * S];
__device__ __align__(16) __nv_bfloat16 g_hh [(size_t)NZ * RC * S];
__device__ __align__(16) __nv_bfloat16 g_ah [(size_t)NZ * OC * S];   // exp map
__device__ float g_z [NZ * S];
__device__ float g_pz[(size_t)MG * NZ * S];   // partial column sums

// ---------------- helpers ----------------------------------------------------
#define SW(o) ((o) ^ (((o) >> 3) & 0x70))

__device__ __forceinline__ uint32_t s2u(const void* p) {
    uint32_t a;
    asm("{ .reg .u64 t; cvta.to.shared.u64 t, %1; cvt.u32.u64 %0, t; }"
        : "=r"(a) : "l"(p));
    return a;
}

__device__ __forceinline__ void cpa16(uint32_t s, const void* g) {
    asm volatile("cp.async.cg.shared.global [%0], [%1], 16;" :: "r"(s), "l"(g));
}

#define CP_COMMIT() asm volatile("cp.async.commit_group;" ::: "memory")
#define CP_WAIT0()  asm volatile("cp.async.wait_group 0;" ::: "memory")
#define CP_WAIT1()  asm volatile("cp.async.wait_group 1;" ::: "memory")

#define LDSM4(r, a)                                                            \
    asm volatile("ldmatrix.sync.aligned.m8n8.x4.shared.b16 {%0,%1,%2,%3}, [%4];" \
                 : "=r"((r)[0]), "=r"((r)[1]), "=r"((r)[2]), "=r"((r)[3])      \
                 : "r"(a))

#define LDSM4T(r, a)                                                           \
    asm volatile("ldmatrix.sync.aligned.m8n8.x4.trans.shared.b16 {%0,%1,%2,%3}, [%4];" \
                 : "=r"((r)[0]), "=r"((r)[1]), "=r"((r)[2]), "=r"((r)[3])      \
                 : "r"(a))

__device__ __forceinline__ void mma16816(float* d, const uint32_t* a,
                                         const uint32_t* b) {
    asm volatile(
        "mma.sync.aligned.m16n8k16.row.col.f32.bf16.bf16.f32 "
        "{%0,%1,%2,%3}, {%4,%5,%6,%7}, {%8,%9}, {%0,%1,%2,%3};"
        : "+f"(d[0]), "+f"(d[1]), "+f"(d[2]), "+f"(d[3])
        : "r"(a[0]), "r"(a[1]), "r"(a[2]), "r"(a[3]), "r"(b[0]), "r"(b[1]));
}

// SMEM stage: A 16K | B 16K (two 64-col SW128 halves) = 32K; 3 stages = 96K
static constexpr int STG    = 32768;
static constexpr int OFF_B  = 16384;
static constexpr int SMEM_BYTES = 3 * STG;   // 98304/CTA -> 2 CTAs/SM

enum { EPL_BNRELU = 0, EPL_EXP = 1, EPF_DIV = 2 };

struct GP {
    const __nv_bfloat16 *Ah[2], *Bh[2];
    __nv_bfloat16 *Ch[2];
    float *Cf[2];
    const float *bn[2], *z[2];
    float *psum;
    int M, K, N;
    size_t aBS, bBS, cBS;
};

// ======== bf16 tensor GEMM (both branches): C = A @ B =======================
// CTA tile 128x128, 8 warps (4x2), warp tile 32x64, K-chunk 64, 2 CTAs/SM,
// 3-stage cp.async ring with ONE barrier per chunk (top, after wait).
// Safety: prefetch after barrier ci writes stage (ci+2)%3 == (ci-1)%3, whose
// readers all finished before any warp passed barrier ci; visibility of
// chunk ci is ordered by wait_group->barrier->read.
template <int EP>
__global__ void __launch_bounds__(256, 2)
gemm_mma(GP p)
{
    extern __shared__ char smem[];
    const uint32_t sb = s2u(smem);
    const int t = threadIdx.x, wid = t >> 5, lane = t & 31;
    const int br = blockIdx.z >> 1, bz = blockIdx.z & 1;
    const int m0 = blockIdx.y * 128, n0 = blockIdx.x * 128;
    const int wm0 = (wid >> 1) * 32, wn0 = (wid & 1) * 64;
    const int K = p.K, N = p.N;

    const __nv_bfloat16* Abh = p.Ah[br] + bz * p.aBS + (size_t)m0 * K;
    const __nv_bfloat16* Bbh = p.Bh[br] + bz * p.bBS + n0;

    const int a_r = t >> 3, a_c = t & 7;

    auto load_chunk = [&](int k0, int stg) {
        const uint32_t st = sb + stg * STG;
#pragma unroll
        for (int it = 0; it < 4; it++) {
            int row = it * 32 + a_r;
            uint32_t d = (uint32_t)SW(row * 128 + a_c * 16);
            size_t so = (size_t)row * K + k0 + a_c * 8;
            cpa16(st + d, Abh + so);
        }
        // B: 64 k-rows x 128 cols as two 64-col halves (1024 16B chunks)
#pragma unroll
        for (int it = 0; it < 4; it++) {
            int idx = it * 256 + t;
            int row = idx >> 4, c16 = idx & 15;
            int hf = c16 >> 3, c8 = c16 & 7;
            uint32_t d = (uint32_t)(hf * 8192 + SW(row * 128 + c8 * 16));
            size_t so = (size_t)(k0 + row) * N + hf * 64 + c8 * 8;
            cpa16(st + OFF_B + d, Bbh + so);
        }
        CP_COMMIT();
    };

    float acc[2][8][4];
#pragma unroll
    for (int i = 0; i < 2; i++)
#pragma unroll
        for (int j = 0; j < 8; j++)
#pragma unroll
            for (int q = 0; q < 4; q++) acc[i][j][q] = 0.f;

    const int la_r = lane & 15, la_k = lane >> 4;
    const int bt_k = ((lane >> 3) & 1) * 8 + (lane & 7);
    const int bt_n = (lane >> 4) * 8;

    const int nc = K / 64;
    load_chunk(0, 0);
    if (nc > 1) load_chunk(64, 1);

    int stg = 0;
    for (int ci = 0; ci < nc; ci++) {
        if (ci + 1 < nc) { CP_WAIT1(); } else { CP_WAIT0(); }
        __syncthreads();                    // single barrier per chunk
        if (ci + 2 < nc) {
            int s2 = stg + 2; if (s2 >= 3) s2 -= 3;
            load_chunk((ci + 2) * 64, s2);
        }

        const uint32_t st = sb + stg * STG;
#pragma unroll
        for (int ks = 0; ks < 4; ks++) {
            uint32_t ah[2][4], bh[4][4];
#pragma unroll
            for (int i = 0; i < 2; i++) {
                uint32_t d = (uint32_t)SW((wm0 + 16 * i + la_r) * 128 +
                                          ks * 32 + la_k * 16);
                LDSM4(ah[i], st + d);
            }
#pragma unroll
            for (int jj = 0; jj < 4; jj++) {
                int col = wn0 + 16 * jj;
                uint32_t d = (uint32_t)((col >> 6) * 8192 +
                                        SW((ks * 16 + bt_k) * 128 +
                                           ((col & 63) + bt_n) * 2));
                LDSM4T(bh[jj], st + OFF_B + d);
            }
#pragma unroll
            for (int i = 0; i < 2; i++)
#pragma unroll
                for (int j = 0; j < 8; j++)
                    mma16816(acc[i][j], ah[i], &bh[j >> 1][(j & 1) * 2]);
        }
        stg++; if (stg >= 3) stg -= 3;
    }

    // ---------------- epilogue ----------------
    const int g  = lane >> 2;
    const int t2 = lane & 3;

    float cs[8][2];           // column-sum partials (EXP only)
#pragma unroll
    for (int j = 0; j < 8; j++) { cs[j][0] = 0.f; cs[j][1] = 0.f; }

#pragma unroll
    for (int i = 0; i < 2; i++) {
        const int r0 = m0 + wm0 + 16 * i + g;
        const int r1 = r0 + 8;
        float sc0 = 1.f, sh0 = 0.f, sc1 = 1.f, sh1 = 0.f;
        if (EP == EPL_BNRELU) {
            const float* bnp = p.bn[br];
            float ga = bnp[r0], be = bnp[p.M + r0], mu = bnp[2 * p.M + r0], va = bnp[3 * p.M + r0];
            sc0 = ga * rsqrtf(va + 1e-5f);
            sh0 = be - mu * sc0;
            ga = bnp[r1]; be = bnp[p.M + r1]; mu = bnp[2 * p.M + r1]; va = bnp[3 * p.M + r1];
            sc1 = ga * rsqrtf(va + 1e-5f);
            sh1 = be - mu * sc1;
        }
#pragma unroll
        for (int j = 0; j < 8; j++) {
            const int c = n0 + wn0 + 8 * j + t2 * 2;
            float v0 = acc[i][j][0], v1 = acc[i][j][1];
            float v2 = acc[i][j][2], v3 = acc[i][j][3];
            if (EP == EPL_BNRELU) {
                v0 = fmaxf(v0 * sc0 + sh0, 0.f);
                v1 = fmaxf(v1 * sc0 + sh0, 0.f);
                v2 = fmaxf(v2 * sc1 + sh1, 0.f);
                v3 = fmaxf(v3 * sc1 + sh1, 0.f);
            }
            if (EP == EPL_EXP) {
                v0 = __expf(v0); v1 = __expf(v1);
                v2 = __expf(v2); v3 = __expf(v3);
                cs[j][0] += v0 + v2;
                cs[j][1] += v1 + v3;
            }
            if (EP == EPF_DIV) {
                const float* zb = p.z[br] + (size_t)bz * N + c;
                float z0 = zb[0], z1 = zb[1];
                float* Cb = p.Cf[br] + bz * p.cBS;
                *(float2*)(Cb + (size_t)r0 * N + c) = make_float2(v0 / z0, v1 / z1);
                *(float2*)(Cb + (size_t)r1 * N + c) = make_float2(v2 / z0, v3 / z1);
            } else {
                uint32_t h0, h1;
                asm("cvt.rn.bf16x2.f32 %0, %1, %2;" : "=r"(h0) : "f"(v1), "f"(v0));
                asm("cvt.rn.bf16x2.f32 %0, %1, %2;" : "=r"(h1) : "f"(v3), "f"(v2));
                size_t cb0 = bz * p.cBS + (size_t)r0 * N + c;
                size_t cb1 = bz * p.cBS + (size_t)r1 * N + c;
                *(uint32_t*)(p.Ch[br] + cb0) = h0;
                *(uint32_t*)(p.Ch[br] + cb1) = h1;
            }
        }
    }

    if (EP == EPL_EXP) {
        // reduce over the 8 row-lanes (lane bits 2..4) of this warp
#pragma unroll
        for (int off = 4; off < 32; off <<= 1)
#pragma unroll
            for (int j = 0; j < 8; j++) {
                cs[j][0] += __shfl_xor_sync(0xffffffffu, cs[j][0], off);
                cs[j][1] += __shfl_xor_sync(0xffffffffu, cs[j][1], off);
            }
        __syncthreads();            // tile smem no longer needed; reuse it
        float* cs_buf = (float*)smem;   // [8 warps][64 cols]
        if (lane < 4) {
#pragma unroll
            for (int j = 0; j < 8; j++) {
                cs_buf[wid * 64 + 8 * j + 2 * lane]     = cs[j][0];
                cs_buf[wid * 64 + 8 * j + 2 * lane + 1] = cs[j][1];
            }
        }
        __syncthreads();
        if (t < 128) {
            int half = t >> 6, c64 = t & 63;
            float s = 0.f;
#pragma unroll
            for (int rw = 0; rw < 4; rw++)
                s += cs_buf[(rw * 2 + half) * 64 + c64];
            p.psum[(size_t)blockIdx.y * (NZ * S) + (size_t)blockIdx.z * S + n0 + t] = s;
        }
    }
}

// ================= fp32 -> bf16 conversions =================================
__global__ void to_hi(const float4* __restrict__ src, uint2* __restrict__ hi, int n4)
{
    int i = blockIdx.x * blockDim.x + threadIdx.x;
    if (i >= n4) return;
    float4 f = src[i];
    uint2 h;
    asm("cvt.rn.bf16x2.f32 %0, %1, %2;" : "=r"(h.x) : "f"(f.y), "f"(f.x));
    asm("cvt.rn.bf16x2.f32 %0, %1, %2;" : "=r"(h.y) : "f"(f.w), "f"(f.z));
    hi[i] = h;
}

__global__ void to_hi3(const float4* s0, uint2* h0, int n0,
                       const float4* s1, uint2* h1, int n1,
                       const float4* s2, uint2* h2, int n2)
{
    int i = blockIdx.x * blockDim.x + threadIdx.x;
    const float4* s; uint2* hp; int idx;
    if (i < n0)           { s = s0; hp = h0; idx = i; }
    else if (i < n0 + n1) { s = s1; hp = h1; idx = i - n0; }
    else if (i < n0 + n1 + n2) { s = s2; hp = h2; idx = i - n0 - n1; }
    else return;
    float4 f = s[idx];
    uint2 h;
    asm("cvt.rn.bf16x2.f32 %0, %1, %2;" : "=r"(h.x) : "f"(f.y), "f"(f.x));
    asm("cvt.rn.bf16x2.f32 %0, %1, %2;" : "=r"(h.y) : "f"(f.w), "f"(f.z));
    hp[idx] = h;
}

// ============ reduce MG partial column sums -> Z (deterministic) ============
__global__ void reduce_sum(const float* __restrict__ part, float* __restrict__ outv)
{
    const int i = blockIdx.x * blockDim.x + threadIdx.x;
    if (i >= NZ * S) return;
    float v = 0.f;
#pragma unroll
    for (int c = 0; c < MG; c++)
        v += part[(size_t)c * (NZ * S) + i];
    outv[i] = v;
}

// ================= launch ====================================================
extern "C" void kernel_launch(void* const* d_in, const int* in_sizes, int n_in,
                              void* d_out, int out_size)
{
    (void)in_sizes; (void)n_in; (void)out_size;
    const float* x = (const float*)d_in[0];
    float* out = (float*)d_out;

    __nv_bfloat16 *xh, *redh, *hh, *ah;
    __nv_bfloat16 *wrh, *w1h, *w2h;
    float *z_, *pz_;
    cudaGetSymbolAddress((void**)&xh, g_xh);
    cudaGetSymbolAddress((void**)&wrh, g_wrh);
    cudaGetSymbolAddress((void**)&w1h, g_w1h);
    cudaGetSymbolAddress((void**)&w2h, g_w2h);
    cudaGetSymbolAddress((void**)&redh, g_redh);
    cudaGetSymbolAddress((void**)&hh, g_hh);
    cudaGetSymbolAddress((void**)&ah, g_ah);
    cudaGetSymbolAddress((void**)&z_, g_z);
    cudaGetSymbolAddress((void**)&pz_, g_pz);

    const size_t WR = (size_t)RC * CIN, W1 = (size_t)RC * RC, W2 = (size_t)OC * RC;

    cudaFuncSetAttribute((const void*)gemm_mma<EPL_BNRELU>,
                         cudaFuncAttributeMaxDynamicSharedMemorySize, SMEM_BYTES);
    cudaFuncSetAttribute((const void*)gemm_mma<EPL_EXP>,
                         cudaFuncAttributeMaxDynamicSharedMemorySize, SMEM_BYTES);
    cudaFuncSetAttribute((const void*)gemm_mma<EPF_DIV>,
                         cudaFuncAttributeMaxDynamicSharedMemorySize, SMEM_BYTES);

    // [0] x -> bf16
    {
        int n4 = NB * CIN * S / 4;
        to_hi<<<(n4 + 255) / 256, 256>>>((const float4*)x, (uint2*)xh, n4);
    }
    // [1],[2] weights -> bf16
    for (int br = 0; br < 2; br++) {
        const float* wred = (const float*)d_in[1 + br * 5 + 0];
        const float* w1   = (const float*)d_in[1 + br * 5 + 2];
        const float* w2   = (const float*)d_in[1 + br * 5 + 4];
        int n0 = (int)(WR / 4), n1 = (int)(W1 / 4), n2 = (int)(W2 / 4);
        int nb = (n0 + n1 + n2 + 255) / 256;
        to_hi3<<<nb, 256>>>(
            (const float4*)wred, (uint2*)(wrh + br * WR), n0,
            (const float4*)w1,   (uint2*)(w1h + br * W1), n1,
            (const float4*)w2,   (uint2*)(w2h + br * W2), n2);
    }

    const float* bn1c = (const float*)d_in[2];
    const float* bn2c = (const float*)d_in[4];
    const float* bn1d = (const float*)d_in[7];
    const float* bn2d = (const float*)d_in[9];

    GP p{};
    // [3] reduce: red = relu(bn1(wred @ x))
    p.Ah[0] = wrh; p.Ah[1] = wrh + WR;
    p.Bh[0] = p.Bh[1] = xh;
    p.Ch[0] = redh; p.Ch[1] = redh + (size_t)NB * RC * S;
    p.bn[0] = bn1c; p.bn[1] = bn1d;
    p.M = RC; p.K = CIN; p.N = S;
    p.aBS = 0; p.bBS = (size_t)CIN * S; p.cBS = (size_t)RC * S;
    gemm_mma<EPL_BNRELU><<<dim3(S / 128, RC / 128, NZ), 256, SMEM_BYTES>>>(p);

    // [4] conv1: h = relu(bn2(w1 @ red))
    p.Ah[0] = w1h; p.Ah[1] = w1h + W1;
    p.Bh[0] = redh; p.Bh[1] = redh + (size_t)NB * RC * S;
    p.Ch[0] = hh; p.Ch[1] = hh + (size_t)NB * RC * S;
    p.bn[0] = bn2c; p.bn[1] = bn2d;
    p.M = RC; p.K = RC; p.N = S;
    p.aBS = 0; p.bBS = (size_t)RC * S; p.cBS = (size_t)RC * S;
    gemm_mma<EPL_BNRELU><<<dim3(S / 128, RC / 128, NZ), 256, SMEM_BYTES>>>(p);

    // [5] conv2 + fused exp + partial column sums: expA = exp(w2 @ h)
    p.Ah[0] = w2h; p.Ah[1] = w2h + W2;
    p.Bh[0] = hh; p.Bh[1] = hh + (size_t)NB * RC * S;
    p.Ch[0] = ah; p.Ch[1] = ah + (size_t)NB * OC * S;
    p.psum = pz_;
    p.M = OC; p.K = RC; p.N = S;
    p.aBS = 0; p.bBS = (size_t)RC * S; p.cBS = (size_t)OC * S;
    gemm_mma<EPL_EXP><<<dim3(S / 128, OC / 128, NZ), 256, SMEM_BYTES>>>(p);

    // [6] Z = sum of MG partials (deterministic)
    reduce_sum<<<(NZ * S + 255) / 256, 256>>>(pz_, z_);

    // [7] bmm: fm = red @ expA / Z -> out
    p.Ah[0] = redh; p.Ah[1] = redh + (size_t)NB * RC * S;
    p.Bh[0] = ah; p.Bh[1] = ah + (size_t)NB * OC * S;
    p.Cf[0] = out; p.Cf[1] = out + (size_t)RC * S;
    p.z[0] = z_; p.z[1] = z_ + (size_t)NB * S;
    p.M = RC; p.K = S; p.N = S;
    p.aBS = (size_t)RC * S; p.bBS = (size_t)S * S; p.cBS = (size_t)2 * RC * S;
    gemm_mma<EPF_DIV><<<dim3(S / 128, RC / 128, NZ), 256, SMEM_BYTES>>>(p);
}

// round 16
// speedup vs baseline: 1.1117x; 1.0473x over previous
#include <cuda_runtime.h>
#include <cuda_bf16.h>
#include <cstdint>

static constexpr int NB  = 2;
static constexpr int S   = 4096;
static constexpr int CIN = 2048;
static constexpr int RC  = 512;
static constexpr int OC  = 4096;
static constexpr int NZ  = 2 * NB;       // branches x batch
static constexpr int MG  = OC / 128;     // 32 partial-sum row groups (conv2 grid.y)

// ---------------- device scratch (bf16) --------------------------------------
__device__ __align__(16) __nv_bfloat16 g_xh [(size_t)NB * CIN * S];
__device__ __align__(16) __nv_bfloat16 g_wrh[2][(size_t)RC * CIN];
__device__ __align__(16) __nv_bfloat16 g_w1h[2][(size_t)RC * RC];
__device__ __align__(16) __nv_bfloat16 g_w2h[2][(size_t)OC * RC];
__device__ __align__(16) __nv_bfloat16 g_redh[(size_t)NZ * RC * S];
__device__ __align__(16) __nv_bfloat16 g_hh [(size_t)NZ * RC * S];
__device__ __align__(16) __nv_bfloat16 g_ah [(size_t)NZ * OC * S];   // exp map
__device__ float g_z [NZ * S];
__device__ float g_pz[(size_t)MG * NZ * S];   // partial column sums

// ---------------- helpers ----------------------------------------------------
#define SW(o) ((o) ^ (((o) >> 3) & 0x70))

__device__ __forceinline__ uint32_t s2u(const void* p) {
    uint32_t a;
    asm("{ .reg .u64 t; cvta.to.shared.u64 t, %1; cvt.u32.u64 %0, t; }"
        : "=r"(a) : "l"(p));
    return a;
}

__device__ __forceinline__ void cpa16(uint32_t s, const void* g) {
    asm volatile("cp.async.cg.shared.global [%0], [%1], 16;" :: "r"(s), "l"(g));
}

#define CP_COMMIT() asm volatile("cp.async.commit_group;" ::: "memory")
#define CP_WAIT0()  asm volatile("cp.async.wait_group 0;" ::: "memory")
#define CP_WAIT1()  asm volatile("cp.async.wait_group 1;" ::: "memory")

#define LDSM4(r, a)                                                            \
    asm volatile("ldmatrix.sync.aligned.m8n8.x4.shared.b16 {%0,%1,%2,%3}, [%4];" \
                 : "=r"((r)[0]), "=r"((r)[1]), "=r"((r)[2]), "=r"((r)[3])      \
                 : "r"(a))

#define LDSM4T(r, a)                                                           \
    asm volatile("ldmatrix.sync.aligned.m8n8.x4.trans.shared.b16 {%0,%1,%2,%3}, [%4];" \
                 : "=r"((r)[0]), "=r"((r)[1]), "=r"((r)[2]), "=r"((r)[3])      \
                 : "r"(a))

__device__ __forceinline__ void mma16816(float* d, const uint32_t* a,
                                         const uint32_t* b) {
    asm volatile(
        "mma.sync.aligned.m16n8k16.row.col.f32.bf16.bf16.f32 "
        "{%0,%1,%2,%3}, {%4,%5,%6,%7}, {%8,%9}, {%0,%1,%2,%3};"
        : "+f"(d[0]), "+f"(d[1]), "+f"(d[2]), "+f"(d[3])
        : "r"(a[0]), "r"(a[1]), "r"(a[2]), "r"(a[3]), "r"(b[0]), "r"(b[1]));
}

// SMEM stage: A 16K | B 8K = 24K; 3 stages = 72K; 3 CTAs/SM -> 216K/SM
static constexpr int STG    = 24576;
static constexpr int OFF_B  = 16384;
static constexpr int SMEM_BYTES = 3 * STG;

enum { EPL_BNRELU = 0, EPL_EXP = 1, EPF_DIV = 2 };

struct GP {
    const __nv_bfloat16 *Ah[2], *Bh[2];
    __nv_bfloat16 *Ch[2];
    float *Cf[2];
    const float *bn[2], *z[2];
    float *psum;
    int M, K, N;
    size_t aBS, bBS, cBS;
};

// ======== bf16 tensor GEMM (both branches): C = A @ B =======================
// CTA tile 128x64, 8 warps (4x2), warp tile 32x32, K-chunk 64, 3 CTAs/SM
// (24 warps/SM for latency hiding), 3-stage ring, ONE barrier per chunk.
template <int EP>
__global__ void __launch_bounds__(256, 3)
gemm_mma(GP p)
{
    extern __shared__ char smem[];
    const uint32_t sb = s2u(smem);
    const int t = threadIdx.x, wid = t >> 5, lane = t & 31;
    const int br = blockIdx.z >> 1, bz = blockIdx.z & 1;
    const int m0 = blockIdx.y * 128, n0 = blockIdx.x * 64;
    const int wm0 = (wid >> 1) * 32, wn0 = (wid & 1) * 32;
    const int K = p.K, N = p.N;

    const __nv_bfloat16* Abh = p.Ah[br] + bz * p.aBS + (size_t)m0 * K;
    const __nv_bfloat16* Bbh = p.Bh[br] + bz * p.bBS + n0;

    const int a_r = t >> 3, a_c = t & 7;

    auto load_chunk = [&](int k0, int stg) {
        const uint32_t st = sb + stg * STG;
#pragma unroll
        for (int it = 0; it < 4; it++) {
            int row = it * 32 + a_r;
            uint32_t d = (uint32_t)SW(row * 128 + a_c * 16);
            size_t so = (size_t)row * K + k0 + a_c * 8;
            cpa16(st + d, Abh + so);
        }
#pragma unroll
        for (int it = 0; it < 2; it++) {
            int idx = it * 256 + t;
            int row = idx >> 3, nc = idx & 7;
            uint32_t d = (uint32_t)SW(row * 128 + nc * 16);
            size_t so = (size_t)(k0 + row) * N + nc * 8;
            cpa16(st + OFF_B + d, Bbh + so);
        }
        CP_COMMIT();
    };

    float acc[2][4][4];
#pragma unroll
    for (int i = 0; i < 2; i++)
#pragma unroll
        for (int j = 0; j < 4; j++)
#pragma unroll
            for (int q = 0; q < 4; q++) acc[i][j][q] = 0.f;

    const int la_r = lane & 15, la_k = lane >> 4;
    const int bt_k = ((lane >> 3) & 1) * 8 + (lane & 7);
    const int bt_n = (lane >> 4) * 8;

    const int nc = K / 64;
    load_chunk(0, 0);
    if (nc > 1) load_chunk(64, 1);

    int stg = 0;
    for (int ci = 0; ci < nc; ci++) {
        if (ci + 1 < nc) { CP_WAIT1(); } else { CP_WAIT0(); }
        __syncthreads();                   // single barrier per chunk (R15-safe)
        if (ci + 2 < nc) {
            int s2 = stg + 2; if (s2 >= 3) s2 -= 3;
            load_chunk((ci + 2) * 64, s2);
        }

        const uint32_t st = sb + stg * STG;
#pragma unroll
        for (int ks = 0; ks < 4; ks++) {
            uint32_t ah[2][4], bh[2][4];
#pragma unroll
            for (int i = 0; i < 2; i++) {
                uint32_t d = (uint32_t)SW((wm0 + 16 * i + la_r) * 128 +
                                          ks * 32 + la_k * 16);
                LDSM4(ah[i], st + d);
            }
#pragma unroll
            for (int jj = 0; jj < 2; jj++) {
                uint32_t d = (uint32_t)SW((ks * 16 + bt_k) * 128 +
                                          (wn0 + 16 * jj + bt_n) * 2);
                LDSM4T(bh[jj], st + OFF_B + d);
            }
#pragma unroll
            for (int i = 0; i < 2; i++)
#pragma unroll
                for (int j = 0; j < 4; j++)
                    mma16816(acc[i][j], ah[i], &bh[j >> 1][(j & 1) * 2]);
        }
        stg++; if (stg >= 3) stg -= 3;
    }

    // ---------------- epilogue ----------------
    const int g  = lane >> 2;
    const int t2 = lane & 3;

    float cs[4][2];           // column-sum partials (EXP only)
#pragma unroll
    for (int j = 0; j < 4; j++) { cs[j][0] = 0.f; cs[j][1] = 0.f; }

#pragma unroll
    for (int i = 0; i < 2; i++) {
        const int r0 = m0 + wm0 + 16 * i + g;
        const int r1 = r0 + 8;
        float sc0 = 1.f, sh0 = 0.f, sc1 = 1.f, sh1 = 0.f;
        if (EP == EPL_BNRELU) {
            const float* bnp = p.bn[br];
            float ga = bnp[r0], be = bnp[p.M + r0], mu = bnp[2 * p.M + r0], va = bnp[3 * p.M + r0];
            sc0 = ga * rsqrtf(va + 1e-5f);
            sh0 = be - mu * sc0;
            ga = bnp[r1]; be = bnp[p.M + r1]; mu = bnp[2 * p.M + r1]; va = bnp[3 * p.M + r1];
            sc1 = ga * rsqrtf(va + 1e-5f);
            sh1 = be - mu * sc1;
        }
#pragma unroll
        for (int j = 0; j < 4; j++) {
            const int c = n0 + wn0 + 8 * j + t2 * 2;
            float v0 = acc[i][j][0], v1 = acc[i][j][1];
            float v2 = acc[i][j][2], v3 = acc[i][j][3];
            if (EP == EPL_BNRELU) {
                v0 = fmaxf(v0 * sc0 + sh0, 0.f);
                v1 = fmaxf(v1 * sc0 + sh0, 0.f);
                v2 = fmaxf(v2 * sc1 + sh1, 0.f);
                v3 = fmaxf(v3 * sc1 + sh1, 0.f);
            }
            if (EP == EPL_EXP) {
                v0 = __expf(v0); v1 = __expf(v1);
                v2 = __expf(v2); v3 = __expf(v3);
                cs[j][0] += v0 + v2;
                cs[j][1] += v1 + v3;
            }
            if (EP == EPF_DIV) {
                const float* zb = p.z[br] + (size_t)bz * N + c;
                float z0 = zb[0], z1 = zb[1];
                float* Cb = p.Cf[br] + bz * p.cBS;
                *(float2*)(Cb + (size_t)r0 * N + c) = make_float2(v0 / z0, v1 / z1);
                *(float2*)(Cb + (size_t)r1 * N + c) = make_float2(v2 / z0, v3 / z1);
            } else {
                uint32_t h0, h1;
                asm("cvt.rn.bf16x2.f32 %0, %1, %2;" : "=r"(h0) : "f"(v1), "f"(v0));
                asm("cvt.rn.bf16x2.f32 %0, %1, %2;" : "=r"(h1) : "f"(v3), "f"(v2));
                size_t cb0 = bz * p.cBS + (size_t)r0 * N + c;
                size_t cb1 = bz * p.cBS + (size_t)r1 * N + c;
                *(uint32_t*)(p.Ch[br] + cb0) = h0;
                *(uint32_t*)(p.Ch[br] + cb1) = h1;
            }
        }
    }

    if (EP == EPL_EXP) {
        // reduce over the 8 row-lanes (lane bits 2..4) of this warp
#pragma unroll
        for (int off = 4; off < 32; off <<= 1)
#pragma unroll
            for (int j = 0; j < 4; j++) {
                cs[j][0] += __shfl_xor_sync(0xffffffffu, cs[j][0], off);
                cs[j][1] += __shfl_xor_sync(0xffffffffu, cs[j][1], off);
            }
        __syncthreads();            // tile smem no longer needed; reuse it
        float* cs_buf = (float*)smem;   // [8 warps][32 cols]
        if (lane < 4) {
#pragma unroll
            for (int j = 0; j < 4; j++) {
                cs_buf[wid * 32 + 8 * j + 2 * lane]     = cs[j][0];
                cs_buf[wid * 32 + 8 * j + 2 * lane + 1] = cs[j][1];
            }
        }
        __syncthreads();
        if (t < 64) {
            int half = t >> 5, lc = t & 31;
            float s = 0.f;
#pragma unroll
            for (int rw = 0; rw < 4; rw++)
                s += cs_buf[(rw * 2 + half) * 32 + lc];
            p.psum[(size_t)blockIdx.y * (NZ * S) + (size_t)blockIdx.z * S + n0 + t] = s;
        }
    }
}

// ================= fp32 -> bf16 conversions =================================
__global__ void to_hi(const float4* __restrict__ src, uint2* __restrict__ hi, int n4)
{
    int i = blockIdx.x * blockDim.x + threadIdx.x;
    if (i >= n4) return;
    float4 f = src[i];
    uint2 h;
    asm("cvt.rn.bf16x2.f32 %0, %1, %2;" : "=r"(h.x) : "f"(f.y), "f"(f.x));
    asm("cvt.rn.bf16x2.f32 %0, %1, %2;" : "=r"(h.y) : "f"(f.w), "f"(f.z));
    hi[i] = h;
}

__global__ void to_hi3(const float4* s0, uint2* h0, int n0,
                       const float4* s1, uint2* h1, int n1,
                       const float4* s2, uint2* h2, int n2)
{
    int i = blockIdx.x * blockDim.x + threadIdx.x;
    const float4* s; uint2* hp; int idx;
    if (i < n0)           { s = s0; hp = h0; idx = i; }
    else if (i < n0 + n1) { s = s1; hp = h1; idx = i - n0; }
    else if (i < n0 + n1 + n2) { s = s2; hp = h2; idx = i - n0 - n1; }
    else return;
    float4 f = s[idx];
    uint2 h;
    asm("cvt.rn.bf16x2.f32 %0, %1, %2;" : "=r"(h.x) : "f"(f.y), "f"(f.x));
    asm("cvt.rn.bf16x2.f32 %0, %1, %2;" : "=r"(h.y) : "f"(f.w), "f"(f.z));
    hp[idx] = h;
}

// ============ reduce MG partial column sums -> Z (deterministic) ============
__global__ void reduce_sum(const float* __restrict__ part, float* __restrict__ outv)
{
    const int i = blockIdx.x * blockDim.x + threadIdx.x;
    if (i >= NZ * S) return;
    float v = 0.f;
#pragma unroll
    for (int c = 0; c < MG; c++)
        v += part[(size_t)c * (NZ * S) + i];
    outv[i] = v;
}

// ================= launch ====================================================
extern "C" void kernel_launch(void* const* d_in, const int* in_sizes, int n_in,
                              void* d_out, int out_size)
{
    (void)in_sizes; (void)n_in; (void)out_size;
    const float* x = (const float*)d_in[0];
    float* out = (float*)d_out;

    __nv_bfloat16 *xh, *redh, *hh, *ah;
    __nv_bfloat16 *wrh, *w1h, *w2h;
    float *z_, *pz_;
    cudaGetSymbolAddress((void**)&xh, g_xh);
    cudaGetSymbolAddress((void**)&wrh, g_wrh);
    cudaGetSymbolAddress((void**)&w1h, g_w1h);
    cudaGetSymbolAddress((void**)&w2h, g_w2h);
    cudaGetSymbolAddress((void**)&redh, g_redh);
    cudaGetSymbolAddress((void**)&hh, g_hh);
    cudaGetSymbolAddress((void**)&ah, g_ah);
    cudaGetSymbolAddress((void**)&z_, g_z);
    cudaGetSymbolAddress((void**)&pz_, g_pz);

    const size_t WR = (size_t)RC * CIN, W1 = (size_t)RC * RC, W2 = (size_t)OC * RC;

    cudaFuncSetAttribute((const void*)gemm_mma<EPL_BNRELU>,
                         cudaFuncAttributeMaxDynamicSharedMemorySize, SMEM_BYTES);
    cudaFuncSetAttribute((const void*)gemm_mma<EPL_EXP>,
                         cudaFuncAttributeMaxDynamicSharedMemorySize, SMEM_BYTES);
    cudaFuncSetAttribute((const void*)gemm_mma<EPF_DIV>,
                         cudaFuncAttributeMaxDynamicSharedMemorySize, SMEM_BYTES);

    // [0] x -> bf16
    {
        int n4 = NB * CIN * S / 4;
        to_hi<<<(n4 + 255) / 256, 256>>>((const float4*)x, (uint2*)xh, n4);
    }
    // [1],[2] weights -> bf16
    for (int br = 0; br < 2; br++) {
        const float* wred = (const float*)d_in[1 + br * 5 + 0];
        const float* w1   = (const float*)d_in[1 + br * 5 + 2];
        const float* w2   = (const float*)d_in[1 + br * 5 + 4];
        int n0 = (int)(WR / 4), n1 = (int)(W1 / 4), n2 = (int)(W2 / 4);
        int nb = (n0 + n1 + n2 + 255) / 256;
        to_hi3<<<nb, 256>>>(
            (const float4*)wred, (uint2*)(wrh + br * WR), n0,
            (const float4*)w1,   (uint2*)(w1h + br * W1), n1,
            (const float4*)w2,   (uint2*)(w2h + br * W2), n2);
    }

    const float* bn1c = (const float*)d_in[2];
    const float* bn2c = (const float*)d_in[4];
    const float* bn1d = (const float*)d_in[7];
    const float* bn2d = (const float*)d_in[9];

    GP p{};
    // [3] reduce: red = relu(bn1(wred @ x))
    p.Ah[0] = wrh; p.Ah[1] = wrh + WR;
    p.Bh[0] = p.Bh[1] = xh;
    p.Ch[0] = redh; p.Ch[1] = redh + (size_t)NB * RC * S;
    p.bn[0] = bn1c; p.bn[1] = bn1d;
    p.M = RC; p.K = CIN; p.N = S;
    p.aBS = 0; p.bBS = (size_t)CIN * S; p.cBS = (size_t)RC * S;
    gemm_mma<EPL_BNRELU><<<dim3(S / 64, RC / 128, NZ), 256, SMEM_BYTES>>>(p);

    // [4] conv1: h = relu(bn2(w1 @ red))
    p.Ah[0] = w1h; p.Ah[1] = w1h + W1;
    p.Bh[0] = redh; p.Bh[1] = redh + (size_t)NB * RC * S;
    p.Ch[0] = hh; p.Ch[1] = hh + (size_t)NB * RC * S;
    p.bn[0] = bn2c; p.bn[1] = bn2d;
    p.M = RC; p.K = RC; p.N = S;
    p.aBS = 0; p.bBS = (size_t)RC * S; p.cBS = (size_t)RC * S;
    gemm_mma<EPL_BNRELU><<<dim3(S / 64, RC / 128, NZ), 256, SMEM_BYTES>>>(p);

    // [5] conv2 + fused exp + partial column sums: expA = exp(w2 @ h)
    p.Ah[0] = w2h; p.Ah[1] = w2h + W2;
    p.Bh[0] = hh; p.Bh[1] = hh + (size_t)NB * RC * S;
    p.Ch[0] = ah; p.Ch[1] = ah + (size_t)NB * OC * S;
    p.psum = pz_;
    p.M = OC; p.K = RC; p.N = S;
    p.aBS = 0; p.bBS = (size_t)RC * S; p.cBS = (size_t)OC * S;
    gemm_mma<EPL_EXP><<<dim3(S / 64, OC / 128, NZ), 256, SMEM_BYTES>>>(p);

    // [6] Z = sum of MG partials (deterministic)
    reduce_sum<<<(NZ * S + 255) / 256, 256>>>(pz_, z_);

    // [7] bmm: fm = red @ expA / Z -> out
    p.Ah[0] = redh; p.Ah[1] = redh + (size_t)NB * RC * S;
    p.Bh[0] = ah; p.Bh[1] = ah + (size_t)NB * OC * S;
    p.Cf[0] = out; p.Cf[1] = out + (size_t)RC * S;
    p.z[0] = z_; p.z[1] = z_ + (size_t)NB * S;
    p.M = RC; p.K = S; p.N = S;
    p.aBS = (size_t)RC * S; p.bBS = (size_t)S * S; p.cBS = (size_t)2 * RC * S;
    gemm_mma<EPF_DIV><<<dim3(S / 64, RC / 128, NZ), 256, SMEM_BYTES>>>(p);
}